// round 4
// baseline (speedup 1.0000x reference)
#include <cuda_runtime.h>
#include <cuda_bf16.h>
#include <math.h>

#define MAXN 100000
#define MAXE 800000
#define FD 64
#define BN_EPS 1e-5f

typedef unsigned long long ULL;

// ---------------- scratch (no allocations allowed) ----------------
__device__ int   g_cnt[MAXN];
__device__ int   g_off[MAXN + 1];
__device__ int   g_cursor[MAXN];
__device__ int   g_bsum[512];
__device__ float g_dis[MAXN];
__device__ ULL   g_csr[MAXE];     // packed {src:int, norm:float}
__device__ float g_H[(size_t)MAXN * FD];
__device__ float g_G[(size_t)MAXN * FD];
__device__ float g_scale1[FD], g_shift1[FD];
__device__ float g_scale2[FD], g_shift2[FD];
__device__ float g_fb[FD];
__device__ int   g_is64;

// ---------------- init: zero counts + edge dtype detect ----------------
__global__ void k_init(const unsigned int* ei, int n) {
    int i = blockIdx.x * blockDim.x + threadIdx.x;
    if (i < n) g_cnt[i] = 0;
    if (i == 0) {
        int is64 = 1;
        for (int j = 1; j < 64; j += 2)
            if (ei[j] != 0u) { is64 = 0; break; }
        g_is64 = is64;
    }
}

__device__ __forceinline__ int load_idx(const void* ei, long long pos) {
    if (g_is64) return (int)((const long long*)ei)[pos];
    return ((const int*)ei)[pos];
}

__global__ void k_count(const void* ei, int E) {
    int e = blockIdx.x * blockDim.x + threadIdx.x;
    if (e >= E) return;
    int dst = load_idx(ei, (long long)E + e);
    atomicAdd(&g_cnt[dst], 1);
}

// ---------------- constants: BN folds + fused predictor bias ----------------
__global__ void k_consts(const float* b1, const float* g1, const float* bb1,
                         const float* m1, const float* v1,
                         const float* b2, const float* g2, const float* bb2,
                         const float* m2, const float* v2,
                         const float* b3, const float* pW1, const float* pb1) {
    int c = threadIdx.x;
    if (c >= FD) return;
    if (blockIdx.x == 0) {
        float s = g1[c] * rsqrtf(v1[c] + BN_EPS);
        g_scale1[c] = s;
        g_shift1[c] = (b1[c] - m1[c]) * s + bb1[c];
    } else if (blockIdx.x == 1) {
        float s = g2[c] * rsqrtf(v2[c] + BN_EPS);
        g_scale2[c] = s;
        g_shift2[c] = (b2[c] - m2[c]) * s + bb2[c];
    } else {
        float s = pb1[c];
        for (int k = 0; k < FD; k++) s += b3[k] * pW1[k * FD + c];
        g_fb[c] = s;
    }
}

// ---------------- scans ----------------
__global__ void k_scan1(int n) {
    __shared__ int s[256];
    int i = blockIdx.x * 256 + threadIdx.x;
    int v = (i < n) ? g_cnt[i] : 0;
    if (i < n) g_dis[i] = rsqrtf((float)(v + 1));   // +1 self loop
    s[threadIdx.x] = v;
    __syncthreads();
#pragma unroll
    for (int off = 1; off < 256; off <<= 1) {
        int t = (threadIdx.x >= off) ? s[threadIdx.x - off] : 0;
        __syncthreads();
        s[threadIdx.x] += t;
        __syncthreads();
    }
    if (i < n) g_off[i + 1] = s[threadIdx.x];
    if (threadIdx.x == 255) g_bsum[blockIdx.x] = s[255];
}

__global__ void k_scan2(int nb) {
    __shared__ int s[512];
    int t = threadIdx.x;
    int v = (t < nb) ? g_bsum[t] : 0;
    s[t] = v;
    __syncthreads();
#pragma unroll
    for (int off = 1; off < 512; off <<= 1) {
        int u = (t >= off) ? s[t - off] : 0;
        __syncthreads();
        s[t] += u;
        __syncthreads();
    }
    if (t < nb) g_bsum[t] = s[t] - v;   // exclusive
}

__global__ void k_scan3(int n) {
    int i = blockIdx.x * blockDim.x + threadIdx.x;
    if (i < n) {
        int off = g_off[i + 1] + g_bsum[i >> 8];
        g_off[i + 1] = off;
        g_cursor[i] = off - g_cnt[i];
    }
    if (i == 0) g_off[0] = 0;
}

__global__ void k_fill(const void* ei, int E) {
    int e = blockIdx.x * blockDim.x + threadIdx.x;
    if (e >= E) return;
    int s = load_idx(ei, e);
    int d = load_idx(ei, (long long)E + e);
    float norm = g_dis[s] * g_dis[d];
    int pos = atomicAdd(&g_cursor[d], 1);
    g_csr[pos] = (ULL)(unsigned int)s | ((ULL)__float_as_uint(norm) << 32);
}

// ---------------- packed f32x2 helpers ----------------
__device__ __forceinline__ void ffma2(ULL& acc, ULL a, ULL b) {
    asm("fma.rn.f32x2 %0, %1, %2, %0;" : "+l"(acc) : "l"(a), "l"(b));
}
__device__ __forceinline__ ULL dup_f32(float x) {
    ULL r;
    asm("mov.b64 %0, {%1, %1};" : "=l"(r) : "f"(x));
    return r;
}
__device__ __forceinline__ ULL pack2(float a, float b) {
    ULL r;
    asm("mov.b64 %0, {%1, %2};" : "=l"(r) : "f"(a), "f"(b));
    return r;
}
__device__ __forceinline__ float lo_f32(ULL p) { return __uint_as_float((unsigned)p); }
__device__ __forceinline__ float hi_f32(ULL p) { return __uint_as_float((unsigned)(p >> 32)); }

// ---------------- GEMM: Y[n,64] = X[n,64] @ W[64,64] (+ epilogue) ----------------
// 64x64 tile / 256 threads; thread = 2 rows x 8 cols, f32x2 accumulators.
// X stored as dup pairs {x,x}, rows k-rotated: slot(r,k) = (k + 2r) & 63
//   -> warp's 4 row-addresses hit distinct bank quarters (1 phase),
//   -> (k,k+1) pairs contiguous (k even), loaded as one LDS.128.
// W repacked: Wq1[k][tx] = cols {8tx..8tx+3}, Wq2[k][tx] = cols {8tx+4..8tx+7},
//   each ulonglong2 -> LDS.128 over 128 contiguous bytes, conflict-free.
// EPI: 0 = none, 1 = +bias, 2 = tanh(.+bias)
template <int EPI>
__global__ void __launch_bounds__(256)
k_gemm(const float* __restrict__ X, const float* __restrict__ W,
       const float* __restrict__ bias, float* __restrict__ Y, int n) {
    __shared__ ULL Xsd[FD * FD];            // 32 KB
    __shared__ ulonglong2 Wq1[FD * 8];      // 8 KB
    __shared__ ulonglong2 Wq2[FD * 8];      // 8 KB

    int tid = threadIdx.x;
    int row0 = blockIdx.x * FD;

#pragma unroll
    for (int i = 0; i < 4; i++) {
        int idx = tid + i * 256;            // 0..1023
        int k = idx >> 4, c4 = idx & 15;
        float4 w = ((const float4*)W)[idx];
        ulonglong2 wp = make_ulonglong2(pack2(w.x, w.y), pack2(w.z, w.w));
        if (c4 & 1) Wq2[k * 8 + (c4 >> 1)] = wp;
        else        Wq1[k * 8 + (c4 >> 1)] = wp;

        int r = k;                          // same decomposition for X
        int row = row0 + r;
        float4 v = make_float4(0.f, 0.f, 0.f, 0.f);
        if (row < n) v = ((const float4*)(X + (size_t)row * FD))[c4];
        int s0 = (c4 * 4 + 2 * r) & 63;     // even; pair never wraps
        int s1 = (s0 + 2) & 63;
        *(ulonglong2*)&Xsd[r * FD + s0] = make_ulonglong2(dup_f32(v.x), dup_f32(v.y));
        *(ulonglong2*)&Xsd[r * FD + s1] = make_ulonglong2(dup_f32(v.z), dup_f32(v.w));
    }
    __syncthreads();

    int ry = tid >> 3;          // 0..31
    int tx = tid & 7;           // 0..7
    int ra = 2 * ry, rb = ra + 1;
    const ULL* xaB = &Xsd[ra * FD];
    const ULL* xbB = &Xsd[rb * FD];
    int rotA = 2 * ra;          // 4*ry
    int rotB = 2 * rb;          // 4*ry + 2

    ULL acc[2][4];
#pragma unroll
    for (int i = 0; i < 2; i++)
#pragma unroll
        for (int j = 0; j < 4; j++) acc[i][j] = 0ull;

#pragma unroll 8
    for (int k = 0; k < FD; k += 2) {
        ulonglong2 xA = *(const ulonglong2*)&xaB[(k + rotA) & 63];
        ulonglong2 xB = *(const ulonglong2*)&xbB[(k + rotB) & 63];
        ulonglong2 w0a = Wq1[k * 8 + tx];
        ulonglong2 w1a = Wq2[k * 8 + tx];
        ulonglong2 w0b = Wq1[(k + 1) * 8 + tx];
        ulonglong2 w1b = Wq2[(k + 1) * 8 + tx];
        ffma2(acc[0][0], xA.x, w0a.x); ffma2(acc[0][1], xA.x, w0a.y);
        ffma2(acc[0][2], xA.x, w1a.x); ffma2(acc[0][3], xA.x, w1a.y);
        ffma2(acc[1][0], xB.x, w0a.x); ffma2(acc[1][1], xB.x, w0a.y);
        ffma2(acc[1][2], xB.x, w1a.x); ffma2(acc[1][3], xB.x, w1a.y);
        ffma2(acc[0][0], xA.y, w0b.x); ffma2(acc[0][1], xA.y, w0b.y);
        ffma2(acc[0][2], xA.y, w1b.x); ffma2(acc[0][3], xA.y, w1b.y);
        ffma2(acc[1][0], xB.y, w0b.x); ffma2(acc[1][1], xB.y, w0b.y);
        ffma2(acc[1][2], xB.y, w1b.x); ffma2(acc[1][3], xB.y, w1b.y);
    }

    int c0 = tx * 8;
#pragma unroll
    for (int i = 0; i < 2; i++) {
        int row = row0 + ra + i;
        if (row >= n) continue;
        float o[8] = { lo_f32(acc[i][0]), hi_f32(acc[i][0]),
                       lo_f32(acc[i][1]), hi_f32(acc[i][1]),
                       lo_f32(acc[i][2]), hi_f32(acc[i][2]),
                       lo_f32(acc[i][3]), hi_f32(acc[i][3]) };
        if (EPI >= 1) {
#pragma unroll
            for (int j = 0; j < 8; j++) o[j] += bias[c0 + j];
        }
        if (EPI == 2) {
#pragma unroll
            for (int j = 0; j < 8; j++) o[j] = tanhf(o[j]);
        }
        float4* Yp = (float4*)(Y + (size_t)row * FD + c0);
        Yp[0] = make_float4(o[0], o[1], o[2], o[3]);
        Yp[1] = make_float4(o[4], o[5], o[6], o[7]);
    }
}

// ---------------- gather aggregation (CSR), fused self-loop + optional BN/ReLU ----
// One warp per node; lane handles cols [2*lane, 2*lane+1].
// EPI: 0 = plain, 1 = BN1+ReLU, 2 = BN2+ReLU
template <int EPI>
__global__ void __launch_bounds__(256)
k_gather(const float* __restrict__ h, float* __restrict__ out, int n) {
    int node = (blockIdx.x * blockDim.x + threadIdx.x) >> 5;
    int lane = threadIdx.x & 31;
    if (node >= n) return;

    const float2* hp = (const float2*)h;
    float d = g_dis[node];
    float2 acc = hp[(size_t)node * 32 + lane];
    float s2 = d * d;
    acc.x *= s2; acc.y *= s2;

    int e = g_off[node], end = g_off[node + 1];

    for (; e + 4 <= end; e += 4) {
        ULL e0 = g_csr[e + 0];
        ULL e1 = g_csr[e + 1];
        ULL e2 = g_csr[e + 2];
        ULL e3 = g_csr[e + 3];
        float2 v0 = hp[(size_t)(unsigned)e0 * 32 + lane];
        float2 v1 = hp[(size_t)(unsigned)e1 * 32 + lane];
        float2 v2 = hp[(size_t)(unsigned)e2 * 32 + lane];
        float2 v3 = hp[(size_t)(unsigned)e3 * 32 + lane];
        float n0 = __uint_as_float((unsigned)(e0 >> 32));
        float n1 = __uint_as_float((unsigned)(e1 >> 32));
        float n2 = __uint_as_float((unsigned)(e2 >> 32));
        float n3 = __uint_as_float((unsigned)(e3 >> 32));
        acc.x = fmaf(v0.x, n0, acc.x); acc.y = fmaf(v0.y, n0, acc.y);
        acc.x = fmaf(v1.x, n1, acc.x); acc.y = fmaf(v1.y, n1, acc.y);
        acc.x = fmaf(v2.x, n2, acc.x); acc.y = fmaf(v2.y, n2, acc.y);
        acc.x = fmaf(v3.x, n3, acc.x); acc.y = fmaf(v3.y, n3, acc.y);
    }
    for (; e < end; e++) {
        ULL e0 = g_csr[e];
        float2 v0 = hp[(size_t)(unsigned)e0 * 32 + lane];
        float n0 = __uint_as_float((unsigned)(e0 >> 32));
        acc.x = fmaf(v0.x, n0, acc.x); acc.y = fmaf(v0.y, n0, acc.y);
    }

    if (EPI == 1) {
        int c = lane * 2;
        acc.x = fmaxf(fmaf(acc.x, g_scale1[c],     g_shift1[c]),     0.f);
        acc.y = fmaxf(fmaf(acc.y, g_scale1[c + 1], g_shift1[c + 1]), 0.f);
    } else if (EPI == 2) {
        int c = lane * 2;
        acc.x = fmaxf(fmaf(acc.x, g_scale2[c],     g_shift2[c]),     0.f);
        acc.y = fmaxf(fmaf(acc.y, g_scale2[c + 1], g_shift2[c + 1]), 0.f);
    }
    ((float2*)out)[(size_t)node * 32 + lane] = acc;
}

// ---------------- launch ----------------
extern "C" void kernel_launch(void* const* d_in, const int* in_sizes, int n_in,
                              void* d_out, int out_size) {
    const float* x    = (const float*)d_in[0];
    const void*  ei   = d_in[1];
    const float* W1   = (const float*)d_in[2];
    const float* b1   = (const float*)d_in[3];
    const float* W2   = (const float*)d_in[4];
    const float* b2   = (const float*)d_in[5];
    const float* W3   = (const float*)d_in[6];
    const float* b3   = (const float*)d_in[7];
    const float* bn1g = (const float*)d_in[8];
    const float* bn1b = (const float*)d_in[9];
    const float* bn1m = (const float*)d_in[10];
    const float* bn1v = (const float*)d_in[11];
    const float* bn2g = (const float*)d_in[12];
    const float* bn2b = (const float*)d_in[13];
    const float* bn2m = (const float*)d_in[14];
    const float* bn2v = (const float*)d_in[15];
    const float* pW1  = (const float*)d_in[16];
    const float* pb1  = (const float*)d_in[17];
    const float* pW2  = (const float*)d_in[18];
    const float* pb2  = (const float*)d_in[19];
    float* out = (float*)d_out;

    int n = in_sizes[0] / FD;
    int E = in_sizes[1] / 2;
    if (n > MAXN) n = MAXN;
    if (E > MAXE) E = MAXE;

    float *H, *G, *FB;
    cudaGetSymbolAddress((void**)&H,  g_H);
    cudaGetSymbolAddress((void**)&G,  g_G);
    cudaGetSymbolAddress((void**)&FB, g_fb);

    const int TB = 256;
    int gb_n  = (n + TB - 1) / TB;
    int gb_e  = (E + TB - 1) / TB;
    int gb_g  = (n + 63) / 64;            // gemm blocks (64-row tiles)
    int gb_w  = (n + 7) / 8;              // gather blocks (8 warps/block)
    int nb    = (n + 255) / 256;          // scan blocks

    // 1..3: init / count / constants
    k_init<<<gb_n, TB>>>((const unsigned int*)ei, n);
    k_count<<<gb_e, TB>>>(ei, E);
    k_consts<<<3, FD>>>(b1, bn1g, bn1b, bn1m, bn1v,
                        b2, bn2g, bn2b, bn2m, bn2v,
                        b3, pW1, pb1);

    // 4: GEMM1 (profiled launch) — independent of CSR
    k_gemm<0><<<gb_g, TB>>>(x, W1, nullptr, H, n);

    // 5..8: CSR build
    k_scan1<<<nb, 256>>>(n);
    k_scan2<<<1, 512>>>(nb);
    k_scan3<<<gb_n, TB>>>(n);
    k_fill<<<gb_e, TB>>>(ei, E);

    // layer 1 aggregation + BN1/ReLU
    k_gather<1><<<gb_w, TB>>>(H, G, n);

    // layer 2
    k_gemm<0><<<gb_g, TB>>>(G, W2, nullptr, H, n);
    k_gather<2><<<gb_w, TB>>>(H, G, n);

    // layer 3 (b3 folded into predictor bias)
    k_gemm<0><<<gb_g, TB>>>(G, W3, nullptr, H, n);
    k_gather<0><<<gb_w, TB>>>(H, G, n);

    // predictor MLP
    k_gemm<2><<<gb_g, TB>>>(G, pW1, FB, H, n);       // tanh(G @ pW1 + (b3@pW1+pb1))
    k_gemm<1><<<gb_g, TB>>>(H, pW2, pb2, out, n);    // H @ pW2 + pb2
}

// round 5
// speedup vs baseline: 1.3073x; 1.3073x over previous
#include <cuda_runtime.h>
#include <cuda_bf16.h>
#include <math.h>

#define MAXN 100000
#define MAXE 800000
#define FD 64
#define BN_EPS 1e-5f

typedef unsigned long long ULL;

// ---------------- scratch (no allocations allowed) ----------------
__device__ int   g_cnt[MAXN];
__device__ int   g_off[MAXN + 1];
__device__ int   g_cursor[MAXN];
__device__ int   g_bsum[512];
__device__ float g_dis[MAXN];
__device__ ULL   g_csr[MAXE];     // packed {src:int, norm:float}
__device__ float g_H[(size_t)MAXN * FD];
__device__ float g_G[(size_t)MAXN * FD];
__device__ float g_scale1[FD], g_shift1[FD];
__device__ float g_scale2[FD], g_shift2[FD];
__device__ float g_fb[FD];
__device__ int   g_is64;

// ---------------- init: zero counts + edge dtype detect ----------------
__global__ void k_init(const unsigned int* ei, int n) {
    int i = blockIdx.x * blockDim.x + threadIdx.x;
    if (i < n) g_cnt[i] = 0;
    if (i == 0) {
        int is64 = 1;
        for (int j = 1; j < 64; j += 2)
            if (ei[j] != 0u) { is64 = 0; break; }
        g_is64 = is64;
    }
}

__device__ __forceinline__ int load_idx(const void* ei, long long pos) {
    if (g_is64) return (int)((const long long*)ei)[pos];
    return ((const int*)ei)[pos];
}

__global__ void k_count(const void* ei, int E) {
    int e = blockIdx.x * blockDim.x + threadIdx.x;
    if (e >= E) return;
    int dst = load_idx(ei, (long long)E + e);
    atomicAdd(&g_cnt[dst], 1);
}

// ---------------- constants: BN folds + fused predictor bias ----------------
__global__ void k_consts(const float* b1, const float* g1, const float* bb1,
                         const float* m1, const float* v1,
                         const float* b2, const float* g2, const float* bb2,
                         const float* m2, const float* v2,
                         const float* b3, const float* pW1, const float* pb1) {
    int c = threadIdx.x;
    if (c >= FD) return;
    if (blockIdx.x == 0) {
        float s = g1[c] * rsqrtf(v1[c] + BN_EPS);
        g_scale1[c] = s;
        g_shift1[c] = (b1[c] - m1[c]) * s + bb1[c];
    } else if (blockIdx.x == 1) {
        float s = g2[c] * rsqrtf(v2[c] + BN_EPS);
        g_scale2[c] = s;
        g_shift2[c] = (b2[c] - m2[c]) * s + bb2[c];
    } else {
        float s = pb1[c];
        for (int k = 0; k < FD; k++) s += b3[k] * pW1[k * FD + c];
        g_fb[c] = s;
    }
}

// ---------------- scans ----------------
__global__ void k_scan1(int n) {
    __shared__ int s[256];
    int i = blockIdx.x * 256 + threadIdx.x;
    int v = (i < n) ? g_cnt[i] : 0;
    if (i < n) g_dis[i] = rsqrtf((float)(v + 1));   // +1 self loop
    s[threadIdx.x] = v;
    __syncthreads();
#pragma unroll
    for (int off = 1; off < 256; off <<= 1) {
        int t = (threadIdx.x >= off) ? s[threadIdx.x - off] : 0;
        __syncthreads();
        s[threadIdx.x] += t;
        __syncthreads();
    }
    if (i < n) g_off[i + 1] = s[threadIdx.x];
    if (threadIdx.x == 255) g_bsum[blockIdx.x] = s[255];
}

__global__ void k_scan2(int nb) {
    __shared__ int s[512];
    int t = threadIdx.x;
    int v = (t < nb) ? g_bsum[t] : 0;
    s[t] = v;
    __syncthreads();
#pragma unroll
    for (int off = 1; off < 512; off <<= 1) {
        int u = (t >= off) ? s[t - off] : 0;
        __syncthreads();
        s[t] += u;
        __syncthreads();
    }
    if (t < nb) g_bsum[t] = s[t] - v;   // exclusive
}

__global__ void k_scan3(int n) {
    int i = blockIdx.x * blockDim.x + threadIdx.x;
    if (i < n) {
        int off = g_off[i + 1] + g_bsum[i >> 8];
        g_off[i + 1] = off;
        g_cursor[i] = off - g_cnt[i];
    }
    if (i == 0) g_off[0] = 0;
}

__global__ void k_fill(const void* ei, int E) {
    int e = blockIdx.x * blockDim.x + threadIdx.x;
    if (e >= E) return;
    int s = load_idx(ei, e);
    int d = load_idx(ei, (long long)E + e);
    float norm = g_dis[s] * g_dis[d];
    int pos = atomicAdd(&g_cursor[d], 1);
    g_csr[pos] = (ULL)(unsigned int)s | ((ULL)__float_as_uint(norm) << 32);
}

// ---------------- packed f32x2 helpers ----------------
__device__ __forceinline__ void ffma2(ULL& acc, ULL a, ULL b) {
    asm("fma.rn.f32x2 %0, %1, %2, %0;" : "+l"(acc) : "l"(a), "l"(b));
}
__device__ __forceinline__ ULL dup_f32(float x) {
    ULL r;
    asm("mov.b64 %0, {%1, %1};" : "=l"(r) : "f"(x));
    return r;
}
__device__ __forceinline__ ULL pack2(float a, float b) {
    ULL r;
    asm("mov.b64 %0, {%1, %2};" : "=l"(r) : "f"(a), "f"(b));
    return r;
}
__device__ __forceinline__ float lo_f32(ULL p) { return __uint_as_float((unsigned)p); }
__device__ __forceinline__ float hi_f32(ULL p) { return __uint_as_float((unsigned)(p >> 32)); }

// ---------------- GEMM: Y[n,64] = X[n,64] @ W[64,64] (+ epilogue) ----------------
// 128-row tile / 128 threads. Thread = 8 rows x 8 cols, f32x2 accumulators (64 regs).
// Thread rows strided by 16: r_i = ty + 16*i -> warp's 4 row-addresses differ by
// 68 words (distinct banks), X loads are LDS.128 with immediate offsets only.
// W repacked: Wq1[k*8+t] = cols {8t..8t+3} as {w0,w1},{w2,w3}; Wq2 = cols {8t+4..8t+7}.
// Per 4-k chunk/thread: 16 LDS.128 + 32 dup-mov + 128 FFMA2 -> 0.5 B(LDS)/FMA.
// EPI: 0 = none, 1 = +bias, 2 = tanh(.+bias)
#define XS_STRIDE 68
#define GEMM_SMEM (128 * XS_STRIDE * 4 + 2 * FD * 8 * 16)

template <int EPI>
__global__ void __launch_bounds__(128)
k_gemm(const float* __restrict__ X, const float* __restrict__ W,
       const float* __restrict__ bias, float* __restrict__ Y, int n) {
    extern __shared__ char smem[];
    float* Xs = (float*)smem;                                   // 128 x 68 floats
    ulonglong2* Wq1 = (ulonglong2*)(smem + 128 * XS_STRIDE * 4);// 64 x 8
    ulonglong2* Wq2 = Wq1 + FD * 8;                             // 64 x 8

    int tid = threadIdx.x;
    int row0 = blockIdx.x * 128;

    // load W: 1024 float4 over 128 threads
#pragma unroll
    for (int i = 0; i < 8; i++) {
        int idx = tid + i * 128;            // 0..1023 = k*16 + c4
        int k = idx >> 4, c4 = idx & 15;
        float4 w = ((const float4*)W)[idx];
        ulonglong2 wp = make_ulonglong2(pack2(w.x, w.y), pack2(w.z, w.w));
        if (c4 & 1) Wq2[k * 8 + (c4 >> 1)] = wp;
        else        Wq1[k * 8 + (c4 >> 1)] = wp;
    }
    // load X tile: 2048 float4 over 128 threads
#pragma unroll
    for (int i = 0; i < 16; i++) {
        int idx = tid + i * 128;            // 0..2047 = r*16 + c4
        int r = idx >> 4, c4 = idx & 15;
        int row = row0 + r;
        float4 v = make_float4(0.f, 0.f, 0.f, 0.f);
        if (row < n) v = ((const float4*)(X + (size_t)row * FD))[c4];
        *(float4*)&Xs[r * XS_STRIDE + c4 * 4] = v;
    }
    __syncthreads();

    int ty = tid >> 3;          // 0..15
    int tx = tid & 7;           // 0..7

    ULL acc[8][4];
#pragma unroll
    for (int i = 0; i < 8; i++)
#pragma unroll
        for (int j = 0; j < 4; j++) acc[i][j] = 0ull;

#pragma unroll 2
    for (int kc = 0; kc < 16; kc++) {       // 4 k per chunk
        float4 xv[8];
#pragma unroll
        for (int i = 0; i < 8; i++)
            xv[i] = *(const float4*)&Xs[(ty + 16 * i) * XS_STRIDE + kc * 4];
#pragma unroll
        for (int dk = 0; dk < 4; dk++) {
            ulonglong2 wA = Wq1[(kc * 4 + dk) * 8 + tx];
            ulonglong2 wB = Wq2[(kc * 4 + dk) * 8 + tx];
#pragma unroll
            for (int i = 0; i < 8; i++) {
                float xs = (dk == 0) ? xv[i].x : (dk == 1) ? xv[i].y
                         : (dk == 2) ? xv[i].z : xv[i].w;
                ULL xd = dup_f32(xs);
                ffma2(acc[i][0], xd, wA.x);
                ffma2(acc[i][1], xd, wA.y);
                ffma2(acc[i][2], xd, wB.x);
                ffma2(acc[i][3], xd, wB.y);
            }
        }
    }

    int c0 = tx * 8;
#pragma unroll
    for (int i = 0; i < 8; i++) {
        int row = row0 + ty + 16 * i;
        if (row >= n) continue;
        float o[8] = { lo_f32(acc[i][0]), hi_f32(acc[i][0]),
                       lo_f32(acc[i][1]), hi_f32(acc[i][1]),
                       lo_f32(acc[i][2]), hi_f32(acc[i][2]),
                       lo_f32(acc[i][3]), hi_f32(acc[i][3]) };
        if (EPI >= 1) {
#pragma unroll
            for (int j = 0; j < 8; j++) o[j] += bias[c0 + j];
        }
        if (EPI == 2) {
#pragma unroll
            for (int j = 0; j < 8; j++) o[j] = tanhf(o[j]);
        }
        float4* Yp = (float4*)(Y + (size_t)row * FD + c0);
        Yp[0] = make_float4(o[0], o[1], o[2], o[3]);
        Yp[1] = make_float4(o[4], o[5], o[6], o[7]);
    }
}

// ---------------- gather aggregation (CSR), fused self-loop + optional BN/ReLU ----
// One warp per node; lane handles cols [2*lane, 2*lane+1].
// EPI: 0 = plain, 1 = BN1+ReLU, 2 = BN2+ReLU
template <int EPI>
__global__ void __launch_bounds__(256)
k_gather(const float* __restrict__ h, float* __restrict__ out, int n) {
    int node = (blockIdx.x * blockDim.x + threadIdx.x) >> 5;
    int lane = threadIdx.x & 31;
    if (node >= n) return;

    const float2* hp = (const float2*)h;
    float d = g_dis[node];
    float2 acc = hp[(size_t)node * 32 + lane];
    float s2 = d * d;
    acc.x *= s2; acc.y *= s2;

    int e = g_off[node], end = g_off[node + 1];

    for (; e + 4 <= end; e += 4) {
        ULL e0 = g_csr[e + 0];
        ULL e1 = g_csr[e + 1];
        ULL e2 = g_csr[e + 2];
        ULL e3 = g_csr[e + 3];
        float2 v0 = hp[(size_t)(unsigned)e0 * 32 + lane];
        float2 v1 = hp[(size_t)(unsigned)e1 * 32 + lane];
        float2 v2 = hp[(size_t)(unsigned)e2 * 32 + lane];
        float2 v3 = hp[(size_t)(unsigned)e3 * 32 + lane];
        float n0 = __uint_as_float((unsigned)(e0 >> 32));
        float n1 = __uint_as_float((unsigned)(e1 >> 32));
        float n2 = __uint_as_float((unsigned)(e2 >> 32));
        float n3 = __uint_as_float((unsigned)(e3 >> 32));
        acc.x = fmaf(v0.x, n0, acc.x); acc.y = fmaf(v0.y, n0, acc.y);
        acc.x = fmaf(v1.x, n1, acc.x); acc.y = fmaf(v1.y, n1, acc.y);
        acc.x = fmaf(v2.x, n2, acc.x); acc.y = fmaf(v2.y, n2, acc.y);
        acc.x = fmaf(v3.x, n3, acc.x); acc.y = fmaf(v3.y, n3, acc.y);
    }
    for (; e < end; e++) {
        ULL e0 = g_csr[e];
        float2 v0 = hp[(size_t)(unsigned)e0 * 32 + lane];
        float n0 = __uint_as_float((unsigned)(e0 >> 32));
        acc.x = fmaf(v0.x, n0, acc.x); acc.y = fmaf(v0.y, n0, acc.y);
    }

    if (EPI == 1) {
        int c = lane * 2;
        acc.x = fmaxf(fmaf(acc.x, g_scale1[c],     g_shift1[c]),     0.f);
        acc.y = fmaxf(fmaf(acc.y, g_scale1[c + 1], g_shift1[c + 1]), 0.f);
    } else if (EPI == 2) {
        int c = lane * 2;
        acc.x = fmaxf(fmaf(acc.x, g_scale2[c],     g_shift2[c]),     0.f);
        acc.y = fmaxf(fmaf(acc.y, g_scale2[c + 1], g_shift2[c + 1]), 0.f);
    }
    ((float2*)out)[(size_t)node * 32 + lane] = acc;
}

// ---------------- launch ----------------
extern "C" void kernel_launch(void* const* d_in, const int* in_sizes, int n_in,
                              void* d_out, int out_size) {
    const float* x    = (const float*)d_in[0];
    const void*  ei   = d_in[1];
    const float* W1   = (const float*)d_in[2];
    const float* b1   = (const float*)d_in[3];
    const float* W2   = (const float*)d_in[4];
    const float* b2   = (const float*)d_in[5];
    const float* W3   = (const float*)d_in[6];
    const float* b3   = (const float*)d_in[7];
    const float* bn1g = (const float*)d_in[8];
    const float* bn1b = (const float*)d_in[9];
    const float* bn1m = (const float*)d_in[10];
    const float* bn1v = (const float*)d_in[11];
    const float* bn2g = (const float*)d_in[12];
    const float* bn2b = (const float*)d_in[13];
    const float* bn2m = (const float*)d_in[14];
    const float* bn2v = (const float*)d_in[15];
    const float* pW1  = (const float*)d_in[16];
    const float* pb1  = (const float*)d_in[17];
    const float* pW2  = (const float*)d_in[18];
    const float* pb2  = (const float*)d_in[19];
    float* out = (float*)d_out;

    int n = in_sizes[0] / FD;
    int E = in_sizes[1] / 2;
    if (n > MAXN) n = MAXN;
    if (E > MAXE) E = MAXE;

    float *H, *G, *FB;
    cudaGetSymbolAddress((void**)&H,  g_H);
    cudaGetSymbolAddress((void**)&G,  g_G);
    cudaGetSymbolAddress((void**)&FB, g_fb);

    // allow >48KB dynamic smem for the GEMM (idempotent; not a stream op)
    cudaFuncSetAttribute(k_gemm<0>, cudaFuncAttributeMaxDynamicSharedMemorySize, GEMM_SMEM);
    cudaFuncSetAttribute(k_gemm<1>, cudaFuncAttributeMaxDynamicSharedMemorySize, GEMM_SMEM);
    cudaFuncSetAttribute(k_gemm<2>, cudaFuncAttributeMaxDynamicSharedMemorySize, GEMM_SMEM);

    const int TB = 256;
    int gb_n  = (n + TB - 1) / TB;
    int gb_e  = (E + TB - 1) / TB;
    int gb_g  = (n + 127) / 128;          // gemm blocks (128-row tiles)
    int gb_w  = (n + 7) / 8;              // gather blocks (8 warps/block)
    int nb    = (n + 255) / 256;          // scan blocks

    // 1..3: init / count / constants
    k_init<<<gb_n, TB>>>((const unsigned int*)ei, n);
    k_count<<<gb_e, TB>>>(ei, E);
    k_consts<<<3, FD>>>(b1, bn1g, bn1b, bn1m, bn1v,
                        b2, bn2g, bn2b, bn2m, bn2v,
                        b3, pW1, pb1);

    // 4: GEMM1 (profiled launch) — independent of CSR
    k_gemm<0><<<gb_g, 128, GEMM_SMEM>>>(x, W1, nullptr, H, n);

    // 5..8: CSR build
    k_scan1<<<nb, 256>>>(n);
    k_scan2<<<1, 512>>>(nb);
    k_scan3<<<gb_n, TB>>>(n);
    k_fill<<<gb_e, TB>>>(ei, E);

    // layer 1 aggregation + BN1/ReLU
    k_gather<1><<<gb_w, TB>>>(H, G, n);

    // layer 2
    k_gemm<0><<<gb_g, 128, GEMM_SMEM>>>(G, W2, nullptr, H, n);
    k_gather<2><<<gb_w, TB>>>(H, G, n);

    // layer 3 (b3 folded into predictor bias)
    k_gemm<0><<<gb_g, 128, GEMM_SMEM>>>(G, W3, nullptr, H, n);
    k_gather<0><<<gb_w, TB>>>(H, G, n);

    // predictor MLP
    k_gemm<2><<<gb_g, 128, GEMM_SMEM>>>(G, pW1, FB, H, n);    // tanh(G @ pW1 + fb)
    k_gemm<1><<<gb_g, 128, GEMM_SMEM>>>(H, pW2, pb2, out, n); // H @ pW2 + pb2
}

// round 6
// speedup vs baseline: 1.3595x; 1.0399x over previous
#include <cuda_runtime.h>
#include <cuda_bf16.h>
#include <math.h>

#define MAXN 100000
#define MAXE 800000
#define FD 64
#define BN_EPS 1e-5f

typedef unsigned long long ULL;

// ---------------- scratch (no allocations allowed) ----------------
__device__ int   g_cnt[MAXN];
__device__ int   g_off[MAXN + 1];
__device__ int   g_cursor[MAXN];
__device__ int   g_bsum[512];
__device__ float g_dis[MAXN];
__device__ ULL   g_csr[MAXE];     // packed {src:int, norm:float}
__device__ float g_H[(size_t)MAXN * FD];
__device__ float g_G[(size_t)MAXN * FD];
__device__ float g_Wm[FD * FD];   // W3 @ pW1 (merged layer-3 / predictor-1 weight)
__device__ float g_scale1[FD], g_shift1[FD];
__device__ float g_scale2[FD], g_shift2[FD];
__device__ float g_fb[FD];
__device__ int   g_is64;

// ---------------- init: zero counts + edge dtype detect ----------------
__global__ void k_init(const unsigned int* ei, int n) {
    int i = blockIdx.x * blockDim.x + threadIdx.x;
    if (i < n) g_cnt[i] = 0;
    if (i == 0) {
        int is64 = 1;
        for (int j = 1; j < 64; j += 2)
            if (ei[j] != 0u) { is64 = 0; break; }
        g_is64 = is64;
    }
}

__device__ __forceinline__ int load_idx(const void* ei, long long pos) {
    if (g_is64) return (int)((const long long*)ei)[pos];
    return ((const int*)ei)[pos];
}

__global__ void k_count(const void* ei, int E) {
    int e = blockIdx.x * blockDim.x + threadIdx.x;
    if (e >= E) return;
    int dst = load_idx(ei, (long long)E + e);
    atomicAdd(&g_cnt[dst], 1);
}

// ---------------- constants: BN folds + fused predictor bias ----------------
__global__ void k_consts(const float* b1, const float* g1, const float* bb1,
                         const float* m1, const float* v1,
                         const float* b2, const float* g2, const float* bb2,
                         const float* m2, const float* v2,
                         const float* b3, const float* pW1, const float* pb1) {
    int c = threadIdx.x;
    if (c >= FD) return;
    if (blockIdx.x == 0) {
        float s = g1[c] * rsqrtf(v1[c] + BN_EPS);
        g_scale1[c] = s;
        g_shift1[c] = (b1[c] - m1[c]) * s + bb1[c];
    } else if (blockIdx.x == 1) {
        float s = g2[c] * rsqrtf(v2[c] + BN_EPS);
        g_scale2[c] = s;
        g_shift2[c] = (b2[c] - m2[c]) * s + bb2[c];
    } else {
        float s = pb1[c];
        for (int k = 0; k < FD; k++) s += b3[k] * pW1[k * FD + c];
        g_fb[c] = s;
    }
}

// ---------------- scans ----------------
__global__ void k_scan1(int n) {
    __shared__ int s[256];
    int i = blockIdx.x * 256 + threadIdx.x;
    int v = (i < n) ? g_cnt[i] : 0;
    if (i < n) g_dis[i] = rsqrtf((float)(v + 1));   // +1 self loop
    s[threadIdx.x] = v;
    __syncthreads();
#pragma unroll
    for (int off = 1; off < 256; off <<= 1) {
        int t = (threadIdx.x >= off) ? s[threadIdx.x - off] : 0;
        __syncthreads();
        s[threadIdx.x] += t;
        __syncthreads();
    }
    if (i < n) g_off[i + 1] = s[threadIdx.x];
    if (threadIdx.x == 255) g_bsum[blockIdx.x] = s[255];
}

__global__ void k_scan2(int nb) {
    __shared__ int s[512];
    int t = threadIdx.x;
    int v = (t < nb) ? g_bsum[t] : 0;
    s[t] = v;
    __syncthreads();
#pragma unroll
    for (int off = 1; off < 512; off <<= 1) {
        int u = (t >= off) ? s[t - off] : 0;
        __syncthreads();
        s[t] += u;
        __syncthreads();
    }
    if (t < nb) g_bsum[t] = s[t] - v;   // exclusive
}

__global__ void k_scan3(int n) {
    int i = blockIdx.x * blockDim.x + threadIdx.x;
    if (i < n) {
        int off = g_off[i + 1] + g_bsum[i >> 8];
        g_off[i + 1] = off;
        g_cursor[i] = off - g_cnt[i];
    }
    if (i == 0) g_off[0] = 0;
}

__global__ void k_fill(const void* ei, int E) {
    int e = blockIdx.x * blockDim.x + threadIdx.x;
    if (e >= E) return;
    int s = load_idx(ei, e);
    int d = load_idx(ei, (long long)E + e);
    float norm = g_dis[s] * g_dis[d];
    int pos = atomicAdd(&g_cursor[d], 1);
    g_csr[pos] = (ULL)(unsigned int)s | ((ULL)__float_as_uint(norm) << 32);
}

// ---------------- packed f32x2 helpers ----------------
__device__ __forceinline__ void ffma2(ULL& acc, ULL a, ULL b) {
    asm("fma.rn.f32x2 %0, %1, %2, %0;" : "+l"(acc) : "l"(a), "l"(b));
}
__device__ __forceinline__ ULL dup_f32(float x) {
    ULL r;
    asm("mov.b64 %0, {%1, %1};" : "=l"(r) : "f"(x));
    return r;
}
__device__ __forceinline__ ULL pack2(float a, float b) {
    ULL r;
    asm("mov.b64 %0, {%1, %2};" : "=l"(r) : "f"(a), "f"(b));
    return r;
}
__device__ __forceinline__ float lo_f32(ULL p) { return __uint_as_float((unsigned)p); }
__device__ __forceinline__ float hi_f32(ULL p) { return __uint_as_float((unsigned)(p >> 32)); }

// ---------------- GEMM: Y[n,64] = X[n,64] @ W[64,64] (+ epilogue) ----------------
// 128-row tiles, 256 threads, grid-stride over tiles (W loaded once per block).
// Thread = 4 rows x 8 cols (f32x2 accumulators). Thread rows r_i = ty + 32*i.
// Warp X loads: 4 distinct row addrs (stride 68 words -> distinct banks), broadcast
// across tx -> 1 wavefront. W loads: 8 contiguous 16B -> 128B, broadcast -> 1 wf.
// EPI: 0 = none, 1 = +bias
#define XS_STRIDE 68
#define GEMM_SMEM (128 * XS_STRIDE * 4 + 2 * FD * 8 * 16)

template <int EPI>
__global__ void __launch_bounds__(256, 3)
k_gemm(const float* __restrict__ X, const float* __restrict__ W,
       const float* __restrict__ bias, float* __restrict__ Y, int n, int ntiles) {
    extern __shared__ char smem[];
    float* Xs = (float*)smem;                                    // 128 x 68
    ulonglong2* Wq1 = (ulonglong2*)(smem + 128 * XS_STRIDE * 4); // 64 x 8
    ulonglong2* Wq2 = Wq1 + FD * 8;                              // 64 x 8

    int tid = threadIdx.x;

    // load W once: 1024 float4 over 256 threads
#pragma unroll
    for (int i = 0; i < 4; i++) {
        int idx = tid + i * 256;            // 0..1023 = k*16 + c4
        int k = idx >> 4, c4 = idx & 15;
        float4 w = ((const float4*)W)[idx];
        ulonglong2 wp = make_ulonglong2(pack2(w.x, w.y), pack2(w.z, w.w));
        if (c4 & 1) Wq2[k * 8 + (c4 >> 1)] = wp;
        else        Wq1[k * 8 + (c4 >> 1)] = wp;
    }

    int ty = tid >> 3;          // 0..31
    int tx = tid & 7;           // 0..7
    int c0 = tx * 8;

    for (int t = blockIdx.x; t < ntiles; t += gridDim.x) {
        int row0 = t * 128;
        __syncthreads();        // Xs reuse + (first iter) W visibility

        // load X tile: 2048 float4 over 256 threads
#pragma unroll
        for (int i = 0; i < 8; i++) {
            int idx = tid + i * 256;        // 0..2047 = r*16 + c4
            int r = idx >> 4, c4 = idx & 15;
            int row = row0 + r;
            float4 v = make_float4(0.f, 0.f, 0.f, 0.f);
            if (row < n) v = ((const float4*)(X + (size_t)row * FD))[c4];
            *(float4*)&Xs[r * XS_STRIDE + c4 * 4] = v;
        }
        __syncthreads();

        ULL acc[4][4];
#pragma unroll
        for (int i = 0; i < 4; i++)
#pragma unroll
            for (int j = 0; j < 4; j++) acc[i][j] = 0ull;

#pragma unroll 4
        for (int kc = 0; kc < 16; kc++) {   // 4 k per chunk
            float4 xv[4];
#pragma unroll
            for (int i = 0; i < 4; i++)
                xv[i] = *(const float4*)&Xs[(ty + 32 * i) * XS_STRIDE + kc * 4];
#pragma unroll
            for (int dk = 0; dk < 4; dk++) {
                ulonglong2 wA = Wq1[(kc * 4 + dk) * 8 + tx];
                ulonglong2 wB = Wq2[(kc * 4 + dk) * 8 + tx];
#pragma unroll
                for (int i = 0; i < 4; i++) {
                    float xs = (dk == 0) ? xv[i].x : (dk == 1) ? xv[i].y
                             : (dk == 2) ? xv[i].z : xv[i].w;
                    ULL xd = dup_f32(xs);
                    ffma2(acc[i][0], xd, wA.x);
                    ffma2(acc[i][1], xd, wA.y);
                    ffma2(acc[i][2], xd, wB.x);
                    ffma2(acc[i][3], xd, wB.y);
                }
            }
        }

#pragma unroll
        for (int i = 0; i < 4; i++) {
            int row = row0 + ty + 32 * i;
            if (row >= n) continue;
            float o[8] = { lo_f32(acc[i][0]), hi_f32(acc[i][0]),
                           lo_f32(acc[i][1]), hi_f32(acc[i][1]),
                           lo_f32(acc[i][2]), hi_f32(acc[i][2]),
                           lo_f32(acc[i][3]), hi_f32(acc[i][3]) };
            if (EPI >= 1) {
#pragma unroll
                for (int j = 0; j < 8; j++) o[j] += bias[c0 + j];
            }
            float4* Yp = (float4*)(Y + (size_t)row * FD + c0);
            Yp[0] = make_float4(o[0], o[1], o[2], o[3]);
            Yp[1] = make_float4(o[4], o[5], o[6], o[7]);
        }
    }
}

// ---------------- gather aggregation (CSR), fused self-loop + epilogue ----------
// One warp per node; lane handles cols [2*lane, 2*lane+1].
// EPI: 0 = plain, 1 = BN1+ReLU, 2 = BN2+ReLU, 3 = tanh(. + fb)
template <int EPI>
__global__ void __launch_bounds__(256)
k_gather(const float* __restrict__ h, float* __restrict__ out, int n) {
    int node = (blockIdx.x * blockDim.x + threadIdx.x) >> 5;
    int lane = threadIdx.x & 31;
    if (node >= n) return;

    const float2* hp = (const float2*)h;
    float d = g_dis[node];
    float2 acc = hp[(size_t)node * 32 + lane];
    float s2 = d * d;
    acc.x *= s2; acc.y *= s2;

    int e = g_off[node], end = g_off[node + 1];

    for (; e + 4 <= end; e += 4) {
        ULL e0 = g_csr[e + 0];
        ULL e1 = g_csr[e + 1];
        ULL e2 = g_csr[e + 2];
        ULL e3 = g_csr[e + 3];
        float2 v0 = hp[(size_t)(unsigned)e0 * 32 + lane];
        float2 v1 = hp[(size_t)(unsigned)e1 * 32 + lane];
        float2 v2 = hp[(size_t)(unsigned)e2 * 32 + lane];
        float2 v3 = hp[(size_t)(unsigned)e3 * 32 + lane];
        float n0 = __uint_as_float((unsigned)(e0 >> 32));
        float n1 = __uint_as_float((unsigned)(e1 >> 32));
        float n2 = __uint_as_float((unsigned)(e2 >> 32));
        float n3 = __uint_as_float((unsigned)(e3 >> 32));
        acc.x = fmaf(v0.x, n0, acc.x); acc.y = fmaf(v0.y, n0, acc.y);
        acc.x = fmaf(v1.x, n1, acc.x); acc.y = fmaf(v1.y, n1, acc.y);
        acc.x = fmaf(v2.x, n2, acc.x); acc.y = fmaf(v2.y, n2, acc.y);
        acc.x = fmaf(v3.x, n3, acc.x); acc.y = fmaf(v3.y, n3, acc.y);
    }
    for (; e < end; e++) {
        ULL e0 = g_csr[e];
        float2 v0 = hp[(size_t)(unsigned)e0 * 32 + lane];
        float n0 = __uint_as_float((unsigned)(e0 >> 32));
        acc.x = fmaf(v0.x, n0, acc.x); acc.y = fmaf(v0.y, n0, acc.y);
    }

    int c = lane * 2;
    if (EPI == 1) {
        acc.x = fmaxf(fmaf(acc.x, g_scale1[c],     g_shift1[c]),     0.f);
        acc.y = fmaxf(fmaf(acc.y, g_scale1[c + 1], g_shift1[c + 1]), 0.f);
    } else if (EPI == 2) {
        acc.x = fmaxf(fmaf(acc.x, g_scale2[c],     g_shift2[c]),     0.f);
        acc.y = fmaxf(fmaf(acc.y, g_scale2[c + 1], g_shift2[c + 1]), 0.f);
    } else if (EPI == 3) {
        acc.x = tanhf(acc.x + g_fb[c]);
        acc.y = tanhf(acc.y + g_fb[c + 1]);
    }
    ((float2*)out)[(size_t)node * 32 + lane] = acc;
}

// ---------------- launch ----------------
extern "C" void kernel_launch(void* const* d_in, const int* in_sizes, int n_in,
                              void* d_out, int out_size) {
    const float* x    = (const float*)d_in[0];
    const void*  ei   = d_in[1];
    const float* W1   = (const float*)d_in[2];
    const float* b1   = (const float*)d_in[3];
    const float* W2   = (const float*)d_in[4];
    const float* b2   = (const float*)d_in[5];
    const float* W3   = (const float*)d_in[6];
    const float* b3   = (const float*)d_in[7];
    const float* bn1g = (const float*)d_in[8];
    const float* bn1b = (const float*)d_in[9];
    const float* bn1m = (const float*)d_in[10];
    const float* bn1v = (const float*)d_in[11];
    const float* bn2g = (const float*)d_in[12];
    const float* bn2b = (const float*)d_in[13];
    const float* bn2m = (const float*)d_in[14];
    const float* bn2v = (const float*)d_in[15];
    const float* pW1  = (const float*)d_in[16];
    const float* pb1  = (const float*)d_in[17];
    const float* pW2  = (const float*)d_in[18];
    const float* pb2  = (const float*)d_in[19];
    float* out = (float*)d_out;

    int n = in_sizes[0] / FD;
    int E = in_sizes[1] / 2;
    if (n > MAXN) n = MAXN;
    if (E > MAXE) E = MAXE;

    float *H, *G, *WM;
    cudaGetSymbolAddress((void**)&H,  g_H);
    cudaGetSymbolAddress((void**)&G,  g_G);
    cudaGetSymbolAddress((void**)&WM, g_Wm);

    cudaFuncSetAttribute(k_gemm<0>, cudaFuncAttributeMaxDynamicSharedMemorySize, GEMM_SMEM);
    cudaFuncSetAttribute(k_gemm<1>, cudaFuncAttributeMaxDynamicSharedMemorySize, GEMM_SMEM);

    const int TB = 256;
    int gb_n   = (n + TB - 1) / TB;
    int gb_e   = (E + TB - 1) / TB;
    int ntiles = (n + 127) / 128;         // 128-row gemm tiles
    int gb_g   = (ntiles + 1) / 2;        // 2 tiles per block (wave-balanced)
    int gb_w   = (n + 7) / 8;             // gather blocks (8 warps/block)
    int nb     = (n + 255) / 256;         // scan blocks

    // 1..3: init / count / constants
    k_init<<<gb_n, TB>>>((const unsigned int*)ei, n);
    k_count<<<gb_e, TB>>>(ei, E);
    k_consts<<<3, FD>>>(b1, bn1g, bn1b, bn1m, bn1v,
                        b2, bn2g, bn2b, bn2m, bn2v,
                        b3, pW1, pb1);

    // 4: GEMM1 (profiled launch) — independent of CSR
    k_gemm<0><<<gb_g, TB, GEMM_SMEM>>>(x, W1, nullptr, H, n, ntiles);

    // 5..8: CSR build
    k_scan1<<<nb, 256>>>(n);
    k_scan2<<<1, 512>>>(nb);
    k_scan3<<<gb_n, TB>>>(n);
    k_fill<<<gb_e, TB>>>(ei, E);

    // 9: merged weight Wm = W3 @ pW1 (tiny: one 64-row tile)
    k_gemm<0><<<1, TB, GEMM_SMEM>>>(W3, pW1, nullptr, WM, FD, 1);

    // layer 1 aggregation + BN1/ReLU
    k_gather<1><<<gb_w, TB>>>(H, G, n);

    // layer 2
    k_gemm<0><<<gb_g, TB, GEMM_SMEM>>>(G, W2, nullptr, H, n, ntiles);
    k_gather<2><<<gb_w, TB>>>(H, G, n);

    // layer 3 + predictor-GEMM1 merged: T = tanh(agg(G @ Wm) + fb)
    k_gemm<0><<<gb_g, TB, GEMM_SMEM>>>(G, WM, nullptr, H, n, ntiles);
    k_gather<3><<<gb_w, TB>>>(H, G, n);

    // predictor output GEMM
    k_gemm<1><<<gb_g, TB, GEMM_SMEM>>>(G, pW2, pb2, out, n, ntiles);
}

// round 8
// speedup vs baseline: 1.6937x; 1.2459x over previous
#include <cuda_runtime.h>
#include <cuda_bf16.h>
#include <math.h>
#include <stdint.h>

#define MAXN 100000
#define MAXE 800000
#define FD 64
#define BN_EPS 1e-5f

typedef unsigned long long ULL;

// ---------------- scratch (no allocations allowed) ----------------
__device__ int   g_cnt[MAXN];
__device__ int   g_off[MAXN + 1];
__device__ int   g_cursor[MAXN];
__device__ int   g_bsum[512];
__device__ float g_dis[MAXN];
__device__ ULL   g_csr[MAXE];     // packed {src:int, norm:float}
__device__ float g_H[(size_t)MAXN * FD];
__device__ float g_G[(size_t)MAXN * FD];
__device__ float g_Wm[FD * FD];   // W3 @ pW1 (merged layer-3 / predictor-1 weight)
__device__ float g_scale1[FD], g_shift1[FD];
__device__ float g_scale2[FD], g_shift2[FD];
__device__ float g_fb[FD];
__device__ int   g_is64;

// ---------------- init: zero counts + edge dtype detect ----------------
__global__ void k_init(const unsigned int* ei, int n) {
    int i = blockIdx.x * blockDim.x + threadIdx.x;
    if (i < n) g_cnt[i] = 0;
    if (i == 0) {
        int is64 = 1;
        for (int j = 1; j < 64; j += 2)
            if (ei[j] != 0u) { is64 = 0; break; }
        g_is64 = is64;
    }
}

__device__ __forceinline__ int load_idx(const void* ei, long long pos) {
    if (g_is64) return (int)((const long long*)ei)[pos];
    return ((const int*)ei)[pos];
}

__global__ void k_count(const void* ei, int E) {
    int e = blockIdx.x * blockDim.x + threadIdx.x;
    if (e >= E) return;
    int dst = load_idx(ei, (long long)E + e);
    atomicAdd(&g_cnt[dst], 1);
}

// ---------------- constants: BN folds + fused predictor bias ----------------
__global__ void k_consts(const float* b1, const float* g1, const float* bb1,
                         const float* m1, const float* v1,
                         const float* b2, const float* g2, const float* bb2,
                         const float* m2, const float* v2,
                         const float* b3, const float* pW1, const float* pb1) {
    int c = threadIdx.x;
    if (c >= FD) return;
    if (blockIdx.x == 0) {
        float s = g1[c] * rsqrtf(v1[c] + BN_EPS);
        g_scale1[c] = s;
        g_shift1[c] = (b1[c] - m1[c]) * s + bb1[c];
    } else if (blockIdx.x == 1) {
        float s = g2[c] * rsqrtf(v2[c] + BN_EPS);
        g_scale2[c] = s;
        g_shift2[c] = (b2[c] - m2[c]) * s + bb2[c];
    } else {
        float s = pb1[c];
        for (int k = 0; k < FD; k++) s += b3[k] * pW1[k * FD + c];
        g_fb[c] = s;
    }
}

// ---------------- scans ----------------
__global__ void k_scan1(int n) {
    __shared__ int s[256];
    int i = blockIdx.x * 256 + threadIdx.x;
    int v = (i < n) ? g_cnt[i] : 0;
    if (i < n) g_dis[i] = rsqrtf((float)(v + 1));   // +1 self loop
    s[threadIdx.x] = v;
    __syncthreads();
#pragma unroll
    for (int off = 1; off < 256; off <<= 1) {
        int t = (threadIdx.x >= off) ? s[threadIdx.x - off] : 0;
        __syncthreads();
        s[threadIdx.x] += t;
        __syncthreads();
    }
    if (i < n) g_off[i + 1] = s[threadIdx.x];
    if (threadIdx.x == 255) g_bsum[blockIdx.x] = s[255];
}

__global__ void k_scan2(int nb) {
    __shared__ int s[512];
    int t = threadIdx.x;
    int v = (t < nb) ? g_bsum[t] : 0;
    s[t] = v;
    __syncthreads();
#pragma unroll
    for (int off = 1; off < 512; off <<= 1) {
        int u = (t >= off) ? s[t - off] : 0;
        __syncthreads();
        s[t] += u;
        __syncthreads();
    }
    if (t < nb) g_bsum[t] = s[t] - v;   // exclusive
}

__global__ void k_scan3(int n) {
    int i = blockIdx.x * blockDim.x + threadIdx.x;
    if (i < n) {
        int off = g_off[i + 1] + g_bsum[i >> 8];
        g_off[i + 1] = off;
        g_cursor[i] = off - g_cnt[i];
    }
    if (i == 0) g_off[0] = 0;
}

__global__ void k_fill(const void* ei, int E) {
    int e = blockIdx.x * blockDim.x + threadIdx.x;
    if (e >= E) return;
    int s = load_idx(ei, e);
    int d = load_idx(ei, (long long)E + e);
    float norm = g_dis[s] * g_dis[d];
    int pos = atomicAdd(&g_cursor[d], 1);
    g_csr[pos] = (ULL)(unsigned int)s | ((ULL)__float_as_uint(norm) << 32);
}

// ================= tensor-core GEMM (HMMA mma.sync, split-bf16) =================
// Y[n,64] = X[n,64] @ W[64,64] (+bias). One 128-row tile per block, 256 threads.
// X = Xhi + Xlo (bf16), W = Whi + Wlo (bf16); D = Xhi*Whi + Xhi*Wlo + Xlo*Whi
// accumulated fp32 via mma.sync.m16n8k16.row.col.f32.bf16.bf16.f32.
// smem rows padded to 72 bf16 (144B) -> ldmatrix conflict-free.

#define LDA 72
#define OFF_AHI 0
#define OFF_ALO (128 * LDA * 2)
#define OFF_WHI (2 * 128 * LDA * 2)
#define OFF_WLO (2 * 128 * LDA * 2 + 64 * LDA * 2)
#define TC_SMEM (2 * 128 * LDA * 2 + 2 * 64 * LDA * 2)   // 55296 B

__device__ __forceinline__ uint32_t smem_u32(const void* p) {
    uint32_t a;
    asm("{ .reg .u64 t; cvta.to.shared.u64 t, %1; cvt.u32.u64 %0, t; }"
        : "=r"(a) : "l"(p));
    return a;
}

__device__ __forceinline__ void ldmA(uint32_t addr, uint32_t r[4]) {
    asm volatile("ldmatrix.sync.aligned.m8n8.x4.shared.b16 {%0,%1,%2,%3}, [%4];"
                 : "=r"(r[0]), "=r"(r[1]), "=r"(r[2]), "=r"(r[3]) : "r"(addr));
}
__device__ __forceinline__ void ldmBT(uint32_t addr, uint32_t r[4]) {
    asm volatile("ldmatrix.sync.aligned.m8n8.x4.trans.shared.b16 {%0,%1,%2,%3}, [%4];"
                 : "=r"(r[0]), "=r"(r[1]), "=r"(r[2]), "=r"(r[3]) : "r"(addr));
}
__device__ __forceinline__ void hmma(float d[4], const uint32_t a[4],
                                     uint32_t b0, uint32_t b1) {
    asm volatile(
        "mma.sync.aligned.m16n8k16.row.col.f32.bf16.bf16.f32 "
        "{%0,%1,%2,%3}, {%4,%5,%6,%7}, {%8,%9}, {%0,%1,%2,%3};"
        : "+f"(d[0]), "+f"(d[1]), "+f"(d[2]), "+f"(d[3])
        : "r"(a[0]), "r"(a[1]), "r"(a[2]), "r"(a[3]), "r"(b0), "r"(b1));
}
__device__ __forceinline__ void bf16x2_of(uint32_t& r, float a, float b) {
    asm("cvt.rn.bf16x2.f32 %0, %1, %2;" : "=r"(r) : "f"(b), "f"(a));
}

// EPI: 0 = none, 1 = +bias
template <int EPI>
__global__ void __launch_bounds__(256)
k_gemm_mma(const float* __restrict__ X, const float* __restrict__ W,
           const float* __restrict__ bias, float* __restrict__ Y, int n) {
    extern __shared__ char smem[];
    uint32_t sb = smem_u32(smem);
    int tid = threadIdx.x, w = tid >> 5, lane = tid & 31;
    int row0 = blockIdx.x * 128;

    // ---- W split -> smem [k][n], 4096 elems, 16/thread ----
#pragma unroll
    for (int i = 0; i < 16; i++) {
        int e = tid + i * 256;
        int k = e >> 6, nn = e & 63;
        float v = W[e];
        __nv_bfloat16 h = __float2bfloat16(v);
        __nv_bfloat16 l = __float2bfloat16(v - __bfloat162float(h));
        int off = (k * LDA + nn) * 2;
        *(__nv_bfloat16*)(smem + OFF_WHI + off) = h;
        *(__nv_bfloat16*)(smem + OFF_WLO + off) = l;
    }
    // ---- X tile split -> smem [r][k], 1024 groups of 8 floats, 4/thread ----
#pragma unroll
    for (int i = 0; i < 4; i++) {
        int t = tid + i * 256;
        int r = t >> 3, g = t & 7;
        int row = row0 + r;
        float4 a = make_float4(0.f, 0.f, 0.f, 0.f), b = a;
        if (row < n) {
            const float4* xp = (const float4*)(X + (size_t)row * FD + g * 8);
            a = xp[0]; b = xp[1];
        }
        float f[8] = {a.x, a.y, a.z, a.w, b.x, b.y, b.z, b.w};
        uint32_t hi[4], lo[4];
#pragma unroll
        for (int p = 0; p < 4; p++) {
            uint32_t hw; bf16x2_of(hw, f[2 * p], f[2 * p + 1]);
            float h0 = __uint_as_float(hw << 16);
            float h1 = __uint_as_float(hw & 0xFFFF0000u);
            uint32_t lw; bf16x2_of(lw, f[2 * p] - h0, f[2 * p + 1] - h1);
            hi[p] = hw; lo[p] = lw;
        }
        int off = r * (LDA * 2) + g * 16;
        *(uint4*)(smem + OFF_AHI + off) = make_uint4(hi[0], hi[1], hi[2], hi[3]);
        *(uint4*)(smem + OFF_ALO + off) = make_uint4(lo[0], lo[1], lo[2], lo[3]);
    }
    __syncthreads();

    // fragment base addresses
    uint32_t aA = sb + OFF_AHI + ((w * 16 + (lane & 15)) * LDA + (lane >> 4) * 8) * 2;
    uint32_t aAl = aA + (OFF_ALO - OFF_AHI);
    uint32_t aB = sb + OFF_WHI + ((lane & 15) * LDA + (lane >> 4) * 8) * 2;
    uint32_t aBl = aB + (OFF_WLO - OFF_WHI);

    float acc[8][4];
#pragma unroll
    for (int i = 0; i < 8; i++)
#pragma unroll
        for (int j = 0; j < 4; j++) acc[i][j] = 0.f;

#pragma unroll
    for (int ks = 0; ks < 4; ks++) {
        uint32_t ah[4], al[4];
        ldmA(aA + ks * 32, ah);            // +16 bf16 cols per k-step
        ldmA(aAl + ks * 32, al);
        uint32_t krow = ks * 16 * LDA * 2;
#pragma unroll
        for (int pr = 0; pr < 4; pr++) {   // ntile pair: cols pr*16 .. pr*16+15
            uint32_t bh[4], bl[4];
            ldmBT(aB + krow + pr * 32, bh);
            ldmBT(aBl + krow + pr * 32, bl);
            int nt = pr * 2;
            hmma(acc[nt],     ah, bh[0], bh[1]);
            hmma(acc[nt],     ah, bl[0], bl[1]);
            hmma(acc[nt],     al, bh[0], bh[1]);
            hmma(acc[nt + 1], ah, bh[2], bh[3]);
            hmma(acc[nt + 1], ah, bl[2], bl[3]);
            hmma(acc[nt + 1], al, bh[2], bh[3]);
        }
    }

    // epilogue: C layout m16n8.f32 — {c0,c1} at (lane/4, 2*(lane%4)), {c2,c3} at row+8
    int r0 = row0 + w * 16 + (lane >> 2);
    int cbase = (lane & 3) * 2;
#pragma unroll
    for (int half = 0; half < 2; half++) {
        int row = r0 + half * 8;
        if (row >= n) continue;
        float* yr = Y + (size_t)row * FD;
#pragma unroll
        for (int nt = 0; nt < 8; nt++) {
            int c = nt * 8 + cbase;
            float2 v = make_float2(acc[nt][2 * half], acc[nt][2 * half + 1]);
            if (EPI == 1) { v.x += bias[c]; v.y += bias[c + 1]; }
            *(float2*)(yr + c) = v;
        }
    }
}

// ---------------- gather aggregation (CSR), fused self-loop + epilogue ----------
// One warp per node; lane handles cols [2*lane, 2*lane+1].
// EPI: 0 = plain, 1 = BN1+ReLU, 2 = BN2+ReLU, 3 = tanh(. + fb)
template <int EPI>
__global__ void __launch_bounds__(256)
k_gather(const float* __restrict__ h, float* __restrict__ out, int n) {
    int node = (blockIdx.x * blockDim.x + threadIdx.x) >> 5;
    int lane = threadIdx.x & 31;
    if (node >= n) return;

    const float2* hp = (const float2*)h;
    float d = g_dis[node];
    float2 acc = hp[(size_t)node * 32 + lane];
    float s2 = d * d;
    acc.x *= s2; acc.y *= s2;

    int e = g_off[node], end = g_off[node + 1];

    for (; e + 4 <= end; e += 4) {
        ULL e0 = g_csr[e + 0];
        ULL e1 = g_csr[e + 1];
        ULL e2 = g_csr[e + 2];
        ULL e3 = g_csr[e + 3];
        float2 v0 = hp[(size_t)(unsigned)e0 * 32 + lane];
        float2 v1 = hp[(size_t)(unsigned)e1 * 32 + lane];
        float2 v2 = hp[(size_t)(unsigned)e2 * 32 + lane];
        float2 v3 = hp[(size_t)(unsigned)e3 * 32 + lane];
        float n0 = __uint_as_float((unsigned)(e0 >> 32));
        float n1 = __uint_as_float((unsigned)(e1 >> 32));
        float n2 = __uint_as_float((unsigned)(e2 >> 32));
        float n3 = __uint_as_float((unsigned)(e3 >> 32));
        acc.x = fmaf(v0.x, n0, acc.x); acc.y = fmaf(v0.y, n0, acc.y);
        acc.x = fmaf(v1.x, n1, acc.x); acc.y = fmaf(v1.y, n1, acc.y);
        acc.x = fmaf(v2.x, n2, acc.x); acc.y = fmaf(v2.y, n2, acc.y);
        acc.x = fmaf(v3.x, n3, acc.x); acc.y = fmaf(v3.y, n3, acc.y);
    }
    for (; e < end; e++) {
        ULL e0 = g_csr[e];
        float2 v0 = hp[(size_t)(unsigned)e0 * 32 + lane];
        float n0 = __uint_as_float((unsigned)(e0 >> 32));
        acc.x = fmaf(v0.x, n0, acc.x); acc.y = fmaf(v0.y, n0, acc.y);
    }

    int c = lane * 2;
    if (EPI == 1) {
        acc.x = fmaxf(fmaf(acc.x, g_scale1[c],     g_shift1[c]),     0.f);
        acc.y = fmaxf(fmaf(acc.y, g_scale1[c + 1], g_shift1[c + 1]), 0.f);
    } else if (EPI == 2) {
        acc.x = fmaxf(fmaf(acc.x, g_scale2[c],     g_shift2[c]),     0.f);
        acc.y = fmaxf(fmaf(acc.y, g_scale2[c + 1], g_shift2[c + 1]), 0.f);
    } else if (EPI == 3) {
        acc.x = tanhf(acc.x + g_fb[c]);
        acc.y = tanhf(acc.y + g_fb[c + 1]);
    }
    ((float2*)out)[(size_t)node * 32 + lane] = acc;
}

// ---------------- launch ----------------
extern "C" void kernel_launch(void* const* d_in, const int* in_sizes, int n_in,
                              void* d_out, int out_size) {
    const float* x    = (const float*)d_in[0];
    const void*  ei   = d_in[1];
    const float* W1   = (const float*)d_in[2];
    const float* b1   = (const float*)d_in[3];
    const float* W2   = (const float*)d_in[4];
    const float* b2   = (const float*)d_in[5];
    const float* W3   = (const float*)d_in[6];
    const float* b3   = (const float*)d_in[7];
    const float* bn1g = (const float*)d_in[8];
    const float* bn1b = (const float*)d_in[9];
    const float* bn1m = (const float*)d_in[10];
    const float* bn1v = (const float*)d_in[11];
    const float* bn2g = (const float*)d_in[12];
    const float* bn2b = (const float*)d_in[13];
    const float* bn2m = (const float*)d_in[14];
    const float* bn2v = (const float*)d_in[15];
    const float* pW1  = (const float*)d_in[16];
    const float* pb1  = (const float*)d_in[17];
    const float* pW2  = (const float*)d_in[18];
    const float* pb2  = (const float*)d_in[19];
    float* out = (float*)d_out;

    int n = in_sizes[0] / FD;
    int E = in_sizes[1] / 2;
    if (n > MAXN) n = MAXN;
    if (E > MAXE) E = MAXE;

    float *H, *G, *WM;
    cudaGetSymbolAddress((void**)&H,  g_H);
    cudaGetSymbolAddress((void**)&G,  g_G);
    cudaGetSymbolAddress((void**)&WM, g_Wm);

    cudaFuncSetAttribute(k_gemm_mma<0>, cudaFuncAttributeMaxDynamicSharedMemorySize, TC_SMEM);
    cudaFuncSetAttribute(k_gemm_mma<1>, cudaFuncAttributeMaxDynamicSharedMemorySize, TC_SMEM);

    const int TB = 256;
    int gb_n   = (n + TB - 1) / TB;
    int gb_e   = (E + TB - 1) / TB;
    int ntiles = (n + 127) / 128;         // 128-row gemm tiles
    int gb_w   = (n + 7) / 8;             // gather blocks (8 warps/block)
    int nb     = (n + 255) / 256;         // scan blocks

    // 1..3: init / count / constants
    k_init<<<gb_n, TB>>>((const unsigned int*)ei, n);
    k_count<<<gb_e, TB>>>(ei, E);
    k_consts<<<3, FD>>>(b1, bn1g, bn1b, bn1m, bn1v,
                        b2, bn2g, bn2b, bn2m, bn2v,
                        b3, pW1, pb1);

    // 4: GEMM1 (profiled launch) — independent of CSR
    k_gemm_mma<0><<<ntiles, TB, TC_SMEM>>>(x, W1, nullptr, H, n);

    // 5..8: CSR build
    k_scan1<<<nb, 256>>>(n);
    k_scan2<<<1, 512>>>(nb);
    k_scan3<<<gb_n, TB>>>(n);
    k_fill<<<gb_e, TB>>>(ei, E);

    // 9: merged weight Wm = W3 @ pW1 (one tile)
    k_gemm_mma<0><<<1, TB, TC_SMEM>>>(W3, pW1, nullptr, WM, FD);

    // layer 1 aggregation + BN1/ReLU
    k_gather<1><<<gb_w, TB>>>(H, G, n);

    // layer 2
    k_gemm_mma<0><<<ntiles, TB, TC_SMEM>>>(G, W2, nullptr, H, n);
    k_gather<2><<<gb_w, TB>>>(H, G, n);

    // layer 3 + predictor-GEMM1 merged: T = tanh(agg(G @ Wm) + fb)
    k_gemm_mma<0><<<ntiles, TB, TC_SMEM>>>(G, WM, nullptr, H, n);
    k_gather<3><<<gb_w, TB>>>(H, G, n);

    // predictor output GEMM
    k_gemm_mma<1><<<ntiles, TB, TC_SMEM>>>(G, pW2, pb2, out, n);
}